// round 13
// baseline (speedup 1.0000x reference)
#include <cuda_runtime.h>
#include <stdint.h>

// Shapes (fixed per dataset): B=4, C=128, N_IN=163842, N_OUT=40962
#define BDIM 4
#define CDIM 128
#define EPSV 1e-8f
#define MAX_NOUT 65536
#define CAP 32            // max children per parent (Poisson(4): P(>32) ~ 1e-19)
#define BLOCKS_PER_SM 6
#define TPB 128

// Static scratch (no allocations allowed). __device__ globals are
// zero-initialized at module load; the kernel restores g_count and the
// barrier counters before exiting, so every call sees them zeroed.
__device__ int g_count[MAX_NOUT];
// Packed slot: {child_idx, float_bits(omega)}.
__device__ __align__(16) int2 g_slot[MAX_NOUT * CAP];
// Device-wide barrier counters (phase barrier + cleanup barrier).
__device__ int g_bar1;
__device__ int g_bar2;

// ---------------------------------------------------------------------------
// Fused persistent kernel: build phase -> device-wide barrier -> gather phase.
// Launched at exactly gridDim.x = BLOCKS_PER_SM * numSMs with
// __launch_bounds__(TPB, BLOCKS_PER_SM) guaranteeing full co-residency
// (spin barrier cannot deadlock).
// ---------------------------------------------------------------------------
__global__ void __launch_bounds__(TPB, BLOCKS_PER_SM) fused_kernel(
        const float4* __restrict__ x4,
        const float* __restrict__ omega,
        const void* __restrict__ parent,
        float4* __restrict__ out4,
        int n_in, int n_out) {
    // --- dtype detect (per block, into shared) -----------------------------
    // int64 little-endian with values in [0, 2^31) => all odd 32-bit words 0.
    // 16 independent checks => false-positive probability ~(1/40962)^16 ~ 0.
    __shared__ int s_idx64;
    if (threadIdx.x == 0) {
        const int* p32 = (const int*)parent;
        int all_zero = 1;
#pragma unroll
        for (int k = 0; k < 16; k++)
            if (p32[2 * k + 1] != 0) all_zero = 0;
        s_idx64 = all_zero;
    }
    __syncthreads();

    const int tid      = blockIdx.x * TPB + threadIdx.x;
    const int nthreads = gridDim.x * TPB;

    // --- Phase 1: build (slot fill) ---------------------------------------
    for (int i = tid; i < n_in; i += nthreads) {
        int p = s_idx64 ? (int)((const long long*)parent)[i]
                        : ((const int*)parent)[i];
        float w = omega[i];
        int slot = atomicAdd(&g_count[p], 1);
        if (slot < CAP) {
            g_slot[p * CAP + slot] = make_int2(i, __float_as_int(w));
        }
    }

    // --- Device-wide barrier ----------------------------------------------
    __threadfence();
    __syncthreads();
    if (threadIdx.x == 0) {
        atomicAdd(&g_bar1, 1);
        while (*(volatile int*)&g_bar1 < gridDim.x) { }
        __threadfence();
    }
    __syncthreads();

    // --- Phase 2: gather (warp = output vertex, grid-stride) --------------
    const int warpId = tid >> 5;
    const int l      = tid & 31;
    const int nWarps = nthreads >> 5;
    const long long bs = (long long)n_in * 32;   // float4 stride per batch
    const long long os = (long long)n_out * 32;

    for (int p = warpId; p < n_out; p += nWarps) {
        int deg = g_count[p];
        if (deg > CAP) deg = CAP;   // never fires for this dataset

        float4 a0 = make_float4(0.f, 0.f, 0.f, 0.f);
        float4 a1 = a0, a2 = a0, a3 = a0;
        float den = 0.f;

        const int base_slot = p * CAP;
        for (int k0 = 0; k0 < deg; k0 += 4) {
            // Two 16B broadcast loads = 4 packed slots {idx, w_bits}.
            int4 s01 = *(const int4*)&g_slot[base_slot + k0];
            int4 s23 = *(const int4*)&g_slot[base_slot + k0 + 2];
            int   cidx[4] = {s01.x, s01.z, s23.x, s23.z};
            float cwt[4]  = {__int_as_float(s01.y), __int_as_float(s01.w),
                             __int_as_float(s23.y), __int_as_float(s23.w)};
#pragma unroll
            for (int j = 0; j < 4; j++) {
                if (k0 + j < deg) {
                    float w = cwt[j];
                    den += w;
                    const float4* base = x4 + (long long)cidx[j] * 32 + l;
                    float4 v0 = __ldcs(base);
                    float4 v1 = __ldcs(base + bs);
                    float4 v2 = __ldcs(base + 2 * bs);
                    float4 v3 = __ldcs(base + 3 * bs);
                    a0.x = fmaf(v0.x, w, a0.x); a0.y = fmaf(v0.y, w, a0.y);
                    a0.z = fmaf(v0.z, w, a0.z); a0.w = fmaf(v0.w, w, a0.w);
                    a1.x = fmaf(v1.x, w, a1.x); a1.y = fmaf(v1.y, w, a1.y);
                    a1.z = fmaf(v1.z, w, a1.z); a1.w = fmaf(v1.w, w, a1.w);
                    a2.x = fmaf(v2.x, w, a2.x); a2.y = fmaf(v2.y, w, a2.y);
                    a2.z = fmaf(v2.z, w, a2.z); a2.w = fmaf(v2.w, w, a2.w);
                    a3.x = fmaf(v3.x, w, a3.x); a3.y = fmaf(v3.y, w, a3.y);
                    a3.z = fmaf(v3.z, w, a3.z); a3.w = fmaf(v3.w, w, a3.w);
                }
            }
        }

        // Restore scratch to zero for the next invocation.
        if (l == 0) g_count[p] = 0;

        float inv = 1.0f / fmaxf(den, EPSV);
        a0.x *= inv; a0.y *= inv; a0.z *= inv; a0.w *= inv;
        a1.x *= inv; a1.y *= inv; a1.z *= inv; a1.w *= inv;
        a2.x *= inv; a2.y *= inv; a2.z *= inv; a2.w *= inv;
        a3.x *= inv; a3.y *= inv; a3.z *= inv; a3.w *= inv;

        float4* dst = out4 + (long long)p * 32 + l;
        __stcs(dst,          a0);
        __stcs(dst + os,     a1);
        __stcs(dst + 2 * os, a2);
        __stcs(dst + 3 * os, a3);
    }

    // --- Cleanup barrier: last block resets both counters ------------------
    // A block reaches here only after passing the g_bar1 spin, so when the
    // LAST block arrives, no block can still be reading g_bar1 -> the reset
    // is race-free. Counters are then zero for the next call.
    __syncthreads();
    if (threadIdx.x == 0) {
        int v = atomicAdd(&g_bar2, 1);
        if (v == (int)gridDim.x - 1) {
            g_bar1 = 0;
            g_bar2 = 0;
        }
    }
}

// ---------------------------------------------------------------------------
// Single persistent kernel launch. Grid sized to guaranteed-resident blocks.
// Host-side attribute query runs at capture time; result is fixed per device.
// ---------------------------------------------------------------------------
extern "C" void kernel_launch(void* const* d_in, const int* in_sizes, int n_in_args,
                              void* d_out, int out_size) {
    const float* x      = (const float*)d_in[0];
    const float* omega  = (const float*)d_in[1];
    const void*  parent = d_in[2];

    int n_in  = in_sizes[1];               // omega element count = N_in
    int n_out = out_size / (BDIM * CDIM);  // 40962

    static int n_sms = 0;                  // fixed per device; queried once
    if (n_sms == 0) {
        cudaDeviceGetAttribute(&n_sms, cudaDevAttrMultiProcessorCount, 0);
        if (n_sms <= 0) n_sms = 148;
    }
    int grid = n_sms * BLOCKS_PER_SM;

    fused_kernel<<<grid, TPB>>>((const float4*)x, omega, parent,
                                (float4*)d_out, n_in, n_out);
}

// round 14
// speedup vs baseline: 1.1945x; 1.1945x over previous
#include <cuda_runtime.h>
#include <stdint.h>

// Shapes (fixed per dataset): B=4, C=128, N_IN=163842, N_OUT=40962
#define BDIM 4
#define CDIM 128
#define EPSV 1e-8f
#define MAX_NOUT 65536
#define CAP 32            // max children per parent (Poisson(4): P(>32) ~ 1e-19)

// Static scratch (no allocations allowed). __device__ globals are
// zero-initialized at module load; gather_kernel re-zeroes g_count after
// consuming it, so every kernel_launch call sees it zeroed.
__device__ int g_count[MAX_NOUT];
// Packed slot: {child_idx, float_bits(omega)} — one 8B store in build,
// two slots per 16B broadcast load in gather. Denominator is reconstructed
// in gather by summing slot omegas.
__device__ __align__(16) int2 g_slot[MAX_NOUT * CAP];

// ---------------------------------------------------------------------------
// Build: 4 children per thread, vectorized loads, 4 independent
// atomic->store chains in flight. Fused dtype detect.
// parent_idx dtype: if int64 (little-endian, values in [0, 2^31)), all odd
// 32-bit words are 0. 16 independent checks => false-positive prob ~0.
// ---------------------------------------------------------------------------
__global__ void build_kernel(const float* __restrict__ omega,
                             const void* __restrict__ parent, int n_in) {
    __shared__ int s_idx64;
    if (threadIdx.x == 0) {
        const int* p32 = (const int*)parent;
        int all_zero = 1;
#pragma unroll
        for (int k = 0; k < 16; k++)
            if (p32[2 * k + 1] != 0) all_zero = 0;
        s_idx64 = all_zero;
    }
    __syncthreads();

    int i0 = (blockIdx.x * blockDim.x + threadIdx.x) * 4;
    if (i0 >= n_in) return;

    int   pi[4];
    float wi[4];
    int cnt = min(4, n_in - i0);

    if (!s_idx64 && cnt == 4) {
        // int32 fast path: one 16B load of 4 parents + one 16B omega load.
        int4   p4 = __ldcs((const int4*)((const int*)parent + i0));
        float4 w4 = __ldcs((const float4*)(omega + i0));
        pi[0] = p4.x; pi[1] = p4.y; pi[2] = p4.z; pi[3] = p4.w;
        wi[0] = w4.x; wi[1] = w4.y; wi[2] = w4.z; wi[3] = w4.w;
    } else {
#pragma unroll
        for (int j = 0; j < 4; j++) {
            if (j < cnt) {
                pi[j] = s_idx64 ? (int)((const long long*)parent)[i0 + j]
                                : ((const int*)parent)[i0 + j];
                wi[j] = omega[i0 + j];
            }
        }
    }

#pragma unroll
    for (int j = 0; j < 4; j++) {
        if (j < cnt) {
            int slot = atomicAdd(&g_count[pi[j]], 1);
            if (slot < CAP) {
                g_slot[pi[j] * CAP + slot] =
                    make_int2(i0 + j, __float_as_int(wi[j]));
            }
        }
    }
}

// ---------------------------------------------------------------------------
// Gather (R12, unchanged): one warp per output vertex, lane l covers
// channels [4l, 4l+4), 4 float4 accumulators (one per batch). Children in
// chunks of 4 via two 16B broadcast slot loads -> up to 16 independent
// LDG.128 per lane in flight. Denominator summed locally from slot omegas.
// Streaming hints on bulk streams. Lane 0 restores g_count. Block = 128.
// ---------------------------------------------------------------------------
__global__ void __launch_bounds__(128) gather_kernel(
        const float4* __restrict__ x4,
        float4* __restrict__ out4,
        int n_in, int n_out) {
    int gid = blockIdx.x * blockDim.x + threadIdx.x;
    int p = gid >> 5;
    int l = gid & 31;
    if (p >= n_out) return;

    int deg = g_count[p];
    if (deg > CAP) deg = CAP;   // never fires for this dataset

    float4 a0 = make_float4(0.f, 0.f, 0.f, 0.f);
    float4 a1 = a0, a2 = a0, a3 = a0;
    float den = 0.f;

    const long long bs = (long long)n_in * 32;  // float4 stride per batch
    const int base_slot = p * CAP;

    for (int k0 = 0; k0 < deg; k0 += 4) {
        // Two 16B broadcast loads = 4 packed slots {idx, w_bits}.
        int4 s01 = *(const int4*)&g_slot[base_slot + k0];
        int4 s23 = *(const int4*)&g_slot[base_slot + k0 + 2];
        int   cidx[4] = {s01.x, s01.z, s23.x, s23.z};
        float cwt[4]  = {__int_as_float(s01.y), __int_as_float(s01.w),
                         __int_as_float(s23.y), __int_as_float(s23.w)};
#pragma unroll
        for (int j = 0; j < 4; j++) {
            if (k0 + j < deg) {
                float w = cwt[j];
                den += w;
                const float4* base = x4 + (long long)cidx[j] * 32 + l;
                float4 v0 = __ldcs(base);
                float4 v1 = __ldcs(base + bs);
                float4 v2 = __ldcs(base + 2 * bs);
                float4 v3 = __ldcs(base + 3 * bs);
                a0.x = fmaf(v0.x, w, a0.x); a0.y = fmaf(v0.y, w, a0.y);
                a0.z = fmaf(v0.z, w, a0.z); a0.w = fmaf(v0.w, w, a0.w);
                a1.x = fmaf(v1.x, w, a1.x); a1.y = fmaf(v1.y, w, a1.y);
                a1.z = fmaf(v1.z, w, a1.z); a1.w = fmaf(v1.w, w, a1.w);
                a2.x = fmaf(v2.x, w, a2.x); a2.y = fmaf(v2.y, w, a2.y);
                a2.z = fmaf(v2.z, w, a2.z); a2.w = fmaf(v2.w, w, a2.w);
                a3.x = fmaf(v3.x, w, a3.x); a3.y = fmaf(v3.y, w, a3.y);
                a3.z = fmaf(v3.z, w, a3.z); a3.w = fmaf(v3.w, w, a3.w);
            }
        }
    }

    // Restore scratch to zero for the next invocation (invariant: build
    // always starts from zeroed g_count).
    if (l == 0) {
        g_count[p] = 0;
    }

    float inv = 1.0f / fmaxf(den, EPSV);
    a0.x *= inv; a0.y *= inv; a0.z *= inv; a0.w *= inv;
    a1.x *= inv; a1.y *= inv; a1.z *= inv; a1.w *= inv;
    a2.x *= inv; a2.y *= inv; a2.z *= inv; a2.w *= inv;
    a3.x *= inv; a3.y *= inv; a3.z *= inv; a3.w *= inv;

    const long long os = (long long)n_out * 32;
    float4* dst = out4 + (long long)p * 32 + l;
    __stcs(dst,          a0);
    __stcs(dst + os,     a1);
    __stcs(dst + 2 * os, a2);
    __stcs(dst + 3 * os, a3);
}

// ---------------------------------------------------------------------------
// build -> gather. Default stream, no syncs, no allocations: graph-capturable.
// ---------------------------------------------------------------------------
extern "C" void kernel_launch(void* const* d_in, const int* in_sizes, int n_in_args,
                              void* d_out, int out_size) {
    const float* x      = (const float*)d_in[0];
    const float* omega  = (const float*)d_in[1];
    const void*  parent = d_in[2];

    int n_in  = in_sizes[1];               // omega element count = N_in
    int n_out = out_size / (BDIM * CDIM);  // 40962

    int bthreads = (n_in + 3) / 4;         // 4 children per thread
    build_kernel<<<(bthreads + 127) / 128, 128>>>(omega, parent, n_in);

    int grd = (n_out * 32 + 127) / 128;    // one warp per output vertex
    gather_kernel<<<grd, 128>>>((const float4*)x, (float4*)d_out, n_in, n_out);
}